// round 14
// baseline (speedup 1.0000x reference)
#include <cuda_runtime.h>

#define BB 4096
#define LL 200
#define DD 64
#define STAGES 3    // ring of 2KB stages (4 items each)
#define WPB 4       // warps (= rows) per block
#define NBLK (BB / WPB)

// Transposed fused projection matrices (coalesced matvec access):
// g_MT[j][d]  = M^T  where M = W_item^T @ W_target  (qk = M @ tk)
// g_WvT[j][d] = Wv^T                                 (out = Wv @ vbar)
__device__ float g_MT [DD * DD];
__device__ float g_WvT[DD * DD];

__global__ void precompute_kernel(const float* __restrict__ W_target,
                                  const float* __restrict__ W_item,
                                  const float* __restrict__ W_value) {
    int d  = blockIdx.x;    // 0..63
    int dp = threadIdx.x;   // 0..63
    float s = 0.f;
    #pragma unroll
    for (int e = 0; e < DD; ++e)
        s += W_item[e * DD + d] * W_target[e * DD + dp];
    g_MT[dp * DD + d] = s;                     // M^T
    g_WvT[dp * DD + d] = W_value[d * DD + dp]; // Wv^T
}

__global__ __launch_bounds__(128, 7) void target_attn_kernel(
    const float* __restrict__ tk,    // [B, D]
    const float* __restrict__ ik,    // [B, L, D]
    const float* __restrict__ iv,    // [B, L, D]
    const int*   __restrict__ mask,  // [B, L]
    float* __restrict__ out)         // [B, D]
{
    const int warp = threadIdx.x >> 5;
    const int lane = threadIdx.x & 31;
    const int hl   = lane & 15;      // lane within half-warp (copy addressing)
    const int hsel = lane >> 4;      // 0: items A/C, 1: items B/D
    const int g    = lane >> 3;      // item group 0..3
    const int gl   = lane & 7;       // lane within group
    const int b0   = blockIdx.x * WPB;
    const int b    = b0 + warp;      // this warp compacts/projects row b

    __shared__ __align__(16) float s_pipe[WPB][STAGES][512]; // 2KB stages
    __shared__ __align__(16) float s_q[WPB][DD];
    __shared__ __align__(16) float s_part[WPB][WPB][DD];     // [row][warp][dim]
    __shared__ short s_idx[WPB][LL + 8];
    __shared__ float s_sumw[WPB][WPB];
    __shared__ int   s_nact[WPB];
    __shared__ int   s_nq[WPB];

    // ---- per-warp ballot compaction of own row ----
    const int* mrow = mask + b * LL;
    int base = 0;
    #pragma unroll
    for (int c = 0; c < 7; ++c) {
        const int l = c * 32 + lane;
        const bool act = (l < LL) && (mrow[l] != 0);
        const unsigned bal = __ballot_sync(0xffffffffu, act);
        const int pos = base + __popc(bal & ((1u << lane) - 1u));
        if (act) s_idx[warp][pos] = (short)l;
        base += __popc(bal);
    }
    if (base == 0) {
        // all-masked fallback: softmax(s-1e8)=softmax(s) -> all items active
        #pragma unroll
        for (int c = 0; c < 7; ++c) {
            const int l = c * 32 + lane;
            if (l < LL) s_idx[warp][l] = (short)l;
        }
        base = LL;
    }
    __syncwarp();
    if (lane < 3) s_idx[warp][base + lane] = s_idx[warp][0];  // quad padding
    if (lane == 0) { s_nact[warp] = base; s_nq[warp] = (base + 3) >> 2; }

    // ---- qk = (M @ tk) * (1/sqrt(D)) for own row ----
    {
        float2 t2 = ((const float2*)(tk + (size_t)b * DD))[lane];
        ((float2*)s_q[warp])[lane] = t2;
    }
    __syncwarp();
    {
        float qx = 0.f, qy = 0.f;
        #pragma unroll 8
        for (int j = 0; j < DD; ++j) {
            const float tv = s_q[warp][j];                            // LDS bcast
            const float2 m2 = ((const float2*)(g_MT + j * DD))[lane]; // coalesced
            qx += tv * m2.x;
            qy += tv * m2.y;
        }
        __syncwarp();
        ((float2*)s_q[warp])[lane] = make_float2(qx * 0.125f, qy * 0.125f);
    }

    // ---- zero own flush slots (only this warp writes s_part[*][warp]) ----
    #pragma unroll
    for (int r = 0; r < WPB; ++r) {
        s_part[r][warp][lane]      = 0.f;
        s_part[r][warp][lane + 32] = 0.f;
        if (lane == 0) s_sumw[r][warp] = 0.f;
    }

    __syncthreads();

    // ---- balanced quad ranges over the concatenated 4-row quad list ----
    const int P1 = s_nq[0];
    const int P2 = P1 + s_nq[1];
    const int P3 = P2 + s_nq[2];
    const int Q  = P3 + s_nq[3];
    const int g0 = (Q * warp) >> 2;
    const int g1 = (Q * (warp + 1)) >> 2;

    const unsigned pipe_base =
        (unsigned)__cvta_generic_to_shared(&s_pipe[warp][0][0]);

    // ---- prologue: fill ring ----
    #pragma unroll
    for (int s = 0; s < STAGES; ++s) {
        const int gq = g0 + s;
        if (gq < g1) {
            const int r  = (gq >= P1) + (gq >= P2) + (gq >= P3);
            const int Pr = (r == 0) ? 0 : ((r == 1) ? P1 : ((r == 2) ? P2 : P3));
            const int lq = gq - Pr;
            const short* idxr = s_idx[r];
            const int iAB = idxr[4 * lq + hsel];
            const int iCD = idxr[4 * lq + 2 + hsel];
            const size_t rowbase = (size_t)(b0 + r) * LL;
            const float* pA = ik + (rowbase + iAB) * DD + hl * 4;
            const float* pC = ik + (rowbase + iCD) * DD + hl * 4;
            const float* vA = iv + (rowbase + iAB) * DD + hl * 4;
            const float* vC = iv + (rowbase + iCD) * DD + hl * 4;
            unsigned d = pipe_base + s * 2048 + lane * 16;
            asm volatile(
                "cp.async.cg.shared.global [%0], [%1], 16;\n"
                "cp.async.cg.shared.global [%2], [%3], 16;\n"
                "cp.async.cg.shared.global [%4], [%5], 16;\n"
                "cp.async.cg.shared.global [%6], [%7], 16;\n"
                :: "r"(d), "l"(pA), "r"(d + 512), "l"(pC),
                   "r"(d + 1024), "l"(vA), "r"(d + 1536), "l"(vC) : "memory");
        }
        asm volatile("cp.async.commit_group;" ::: "memory");
    }

    // ---- streaming state ----
    int cur = (g0 >= P1) + (g0 >= P2) + (g0 >= P3);
    float4 q0 = ((const float4*)s_q[cur])[gl];
    float4 q1 = ((const float4*)s_q[cur])[8 + gl];
    int nact_c = s_nact[cur];

    float sum = 0.f;
    float4 acc0 = make_float4(0.f, 0.f, 0.f, 0.f);
    float4 acc1 = make_float4(0.f, 0.f, 0.f, 0.f);

#define FLUSH_ROW(R) do {                                                   \
    float  fs = sum;  float4 f0 = acc0, f1 = acc1;                          \
    _Pragma("unroll")                                                       \
    for (int o = 8; o <= 16; o <<= 1) {                                     \
        fs   += __shfl_xor_sync(0xffffffffu, fs,   o);                      \
        f0.x += __shfl_xor_sync(0xffffffffu, f0.x, o);                      \
        f0.y += __shfl_xor_sync(0xffffffffu, f0.y, o);                      \
        f0.z += __shfl_xor_sync(0xffffffffu, f0.z, o);                      \
        f0.w += __shfl_xor_sync(0xffffffffu, f0.w, o);                      \
        f1.x += __shfl_xor_sync(0xffffffffu, f1.x, o);                      \
        f1.y += __shfl_xor_sync(0xffffffffu, f1.y, o);                      \
        f1.z += __shfl_xor_sync(0xffffffffu, f1.z, o);                      \
        f1.w += __shfl_xor_sync(0xffffffffu, f1.w, o);                      \
    }                                                                       \
    if (lane < 8) {                                                         \
        ((float4*)s_part[R][warp])[lane]     = f0;                          \
        ((float4*)s_part[R][warp])[8 + lane] = f1;                          \
    }                                                                       \
    if (lane == 0) s_sumw[R][warp] = fs;                                    \
} while (0)

    int slot = 0;
    for (int gq = g0; gq < g1; ++gq) {
        const int r  = (gq >= P1) + (gq >= P2) + (gq >= P3);
        const int Pr = (r == 0) ? 0 : ((r == 1) ? P1 : ((r == 2) ? P2 : P3));
        const int lq = gq - Pr;

        if (r != cur) {                       // warp-uniform branch
            FLUSH_ROW(cur);
            cur = r;
            q0 = ((const float4*)s_q[cur])[gl];
            q1 = ((const float4*)s_q[cur])[8 + gl];
            nact_c = s_nact[cur];
            sum = 0.f;
            acc0 = make_float4(0.f, 0.f, 0.f, 0.f);
            acc1 = make_float4(0.f, 0.f, 0.f, 0.f);
        }

        asm volatile("cp.async.wait_group %0;" :: "n"(STAGES - 1) : "memory");

        const float4* stg = (const float4*)&s_pipe[warp][slot][0];
        const float4 a0 = stg[g * 16 + gl];
        const float4 a1 = stg[g * 16 + 8 + gl];
        const float4 v0 = stg[64 + g * 16 + gl];
        const float4 v1 = stg[64 + g * 16 + 8 + gl];

        const int gp = gq + STAGES;
        if (gp < g1) {
            const int rp  = (gp >= P1) + (gp >= P2) + (gp >= P3);
            const int Pp  = (rp == 0) ? 0 : ((rp == 1) ? P1 : ((rp == 2) ? P2 : P3));
            const int lp  = gp - Pp;
            const short* idxr = s_idx[rp];
            const int iAB = idxr[4 * lp + hsel];
            const int iCD = idxr[4 * lp + 2 + hsel];
            const size_t rowbase = (size_t)(b0 + rp) * LL;
            const float* pA = ik + (rowbase + iAB) * DD + hl * 4;
            const float* pC = ik + (rowbase + iCD) * DD + hl * 4;
            const float* vA = iv + (rowbase + iAB) * DD + hl * 4;
            const float* vC = iv + (rowbase + iCD) * DD + hl * 4;
            unsigned d = pipe_base + slot * 2048 + lane * 16;
            asm volatile(
                "cp.async.cg.shared.global [%0], [%1], 16;\n"
                "cp.async.cg.shared.global [%2], [%3], 16;\n"
                "cp.async.cg.shared.global [%4], [%5], 16;\n"
                "cp.async.cg.shared.global [%6], [%7], 16;\n"
                :: "r"(d), "l"(pA), "r"(d + 512), "l"(pC),
                   "r"(d + 1024), "l"(vA), "r"(d + 1536), "l"(vC) : "memory");
        }
        asm volatile("cp.async.commit_group;" ::: "memory");

        // 8-dim partial dot, 3-step butterfly within 8-lane group
        float s = a0.x * q0.x + a0.y * q0.y + a0.z * q0.z + a0.w * q0.w
                + a1.x * q1.x + a1.y * q1.y + a1.z * q1.z + a1.w * q1.w;
        s += __shfl_xor_sync(0xffffffffu, s, 4);
        s += __shfl_xor_sync(0xffffffffu, s, 2);
        s += __shfl_xor_sync(0xffffffffu, s, 1);

        // fixed-max-0 softmax (scores O(1)); padded items get weight 0
        const float w = (4 * lq + g < nact_c) ? __expf(s) : 0.f;
        sum += w;
        acc0.x += w * v0.x; acc0.y += w * v0.y;
        acc0.z += w * v0.z; acc0.w += w * v0.w;
        acc1.x += w * v1.x; acc1.y += w * v1.y;
        acc1.z += w * v1.z; acc1.w += w * v1.w;

        slot = (slot == STAGES - 1) ? 0 : slot + 1;
    }
    FLUSH_ROW(cur);
#undef FLUSH_ROW

    __syncthreads();

    // ---- epilogue: warp w owns output row b0+w ----
    {
        const float tot = s_sumw[warp][0] + s_sumw[warp][1]
                        + s_sumw[warp][2] + s_sumw[warp][3];
        const float invs = 1.f / tot;
        float vx = 0.f, vy = 0.f;
        #pragma unroll
        for (int ws = 0; ws < WPB; ++ws) {
            vx += s_part[warp][ws][2 * lane];
            vy += s_part[warp][ws][2 * lane + 1];
        }
        __syncwarp();
        ((float2*)s_q[warp])[lane] = make_float2(vx * invs, vy * invs);
        __syncwarp();

        float ox = 0.f, oy = 0.f;
        #pragma unroll 8
        for (int j = 0; j < DD; ++j) {
            const float vv = s_q[warp][j];                             // LDS bcast
            const float2 w2 = ((const float2*)(g_WvT + j * DD))[lane]; // coalesced
            ox += vv * w2.x;
            oy += vv * w2.y;
        }
        ((float2*)(out + (size_t)b * DD))[lane] = make_float2(ox, oy);
    }
}

extern "C" void kernel_launch(void* const* d_in, const int* in_sizes, int n_in,
                              void* d_out, int out_size) {
    const float* target_key  = (const float*)d_in[0];
    const float* item_keys   = (const float*)d_in[1];
    const float* item_values = (const float*)d_in[2];
    const int*   mask        = (const int*)  d_in[3];
    const float* W_target    = (const float*)d_in[4];
    const float* W_item      = (const float*)d_in[5];
    const float* W_value     = (const float*)d_in[6];
    float* out = (float*)d_out;

    precompute_kernel<<<DD, DD>>>(W_target, W_item, W_value);
    target_attn_kernel<<<NBLK, 128>>>(target_key, item_keys, item_values,
                                      mask, out);
}

// round 15
// speedup vs baseline: 1.0140x; 1.0140x over previous
#include <cuda_runtime.h>

#define BB 4096
#define LL 200
#define DD 64
#define STAGES 3    // ring of 2KB stages (4 items each)
#define WPB 4       // warps (= rows) per block
#define NBLK (BB / WPB)

// Transposed fused projection matrices (coalesced matvec access):
// g_MT[j][d]  = M^T  where M = W_item^T @ W_target  (qk = M @ tk)
// g_WvT[j][d] = Wv^T                                 (out = Wv @ vbar)
__device__ float g_MT [DD * DD];
__device__ float g_WvT[DD * DD];

__global__ void precompute_kernel(const float* __restrict__ W_target,
                                  const float* __restrict__ W_item,
                                  const float* __restrict__ W_value) {
    int d  = blockIdx.x;    // 0..63
    int dp = threadIdx.x;   // 0..63
    float s = 0.f;
    #pragma unroll
    for (int e = 0; e < DD; ++e)
        s += W_item[e * DD + d] * W_target[e * DD + dp];
    g_MT[dp * DD + d] = s;                     // M^T
    g_WvT[dp * DD + d] = W_value[d * DD + dp]; // Wv^T
}

__global__ __launch_bounds__(128, 7) void target_attn_kernel(
    const float* __restrict__ tk,    // [B, D]
    const float* __restrict__ ik,    // [B, L, D]
    const float* __restrict__ iv,    // [B, L, D]
    const int*   __restrict__ mask,  // [B, L]
    float* __restrict__ out)         // [B, D]
{
    const int warp = threadIdx.x >> 5;
    const int lane = threadIdx.x & 31;
    const int hl   = lane & 15;      // lane within half-warp (copy addressing)
    const int hsel = lane >> 4;      // 0: items A/C, 1: items B/D
    const int g    = lane >> 3;      // item group 0..3
    const int gl   = lane & 7;       // lane within group
    const int b0   = blockIdx.x * WPB;
    const int b    = b0 + warp;      // this warp compacts/projects row b

    __shared__ __align__(16) float s_pipe[WPB][STAGES][512]; // 24KB
    __shared__ __align__(16) float s_q[WPB][DD];             // 1KB
    __shared__ __align__(16) float s_part[WPB][WPB][DD];     // 4KB [row][warp][dim]
    __shared__ short s_flat[4 * WPB * 50 + 8];               // flat quad list
    __shared__ float s_sumw[WPB][WPB];
    __shared__ int   s_cnt[WPB];

    // ---- pass 1: count actives (ballots kept in registers) ----
    const int* mrow = mask + b * LL;
    unsigned bal[7];
    int cnt = 0;
    #pragma unroll
    for (int c = 0; c < 7; ++c) {
        const int l = c * 32 + lane;
        const bool act = (l < LL) && (mrow[l] != 0);
        bal[c] = __ballot_sync(0xffffffffu, act);
        cnt += __popc(bal[c]);
    }
    const bool fb = (cnt == 0);   // all-masked: softmax(s-1e8)=softmax(s)
    if (fb) cnt = LL;
    if (lane == 0) s_cnt[warp] = cnt;

    // ---- qk = (M @ tk) * (1/sqrt(D)) for own row ----
    {
        float2 t2 = ((const float2*)(tk + (size_t)b * DD))[lane];
        ((float2*)s_q[warp])[lane] = t2;
    }
    __syncwarp();
    {
        float qx = 0.f, qy = 0.f;
        #pragma unroll 8
        for (int j = 0; j < DD; ++j) {
            const float tv = s_q[warp][j];                            // LDS bcast
            const float2 m2 = ((const float2*)(g_MT + j * DD))[lane]; // coalesced
            qx += tv * m2.x;
            qy += tv * m2.y;
        }
        __syncwarp();
        ((float2*)s_q[warp])[lane] = make_float2(qx * 0.125f, qy * 0.125f);
    }

    // ---- zero own flush slots ----
    #pragma unroll
    for (int r = 0; r < WPB; ++r) {
        s_part[r][warp][lane]      = 0.f;
        s_part[r][warp][lane + 32] = 0.f;
        if (lane == 0) s_sumw[r][warp] = 0.f;
    }
    __syncthreads();

    // ---- prefix sums of quad counts ----
    const int nq0 = (s_cnt[0] + 3) >> 2;
    const int nq1 = (s_cnt[1] + 3) >> 2;
    const int nq2 = (s_cnt[2] + 3) >> 2;
    const int nq3 = (s_cnt[3] + 3) >> 2;
    int P[WPB + 1];
    P[0] = 0; P[1] = nq0; P[2] = P[1] + nq1; P[3] = P[2] + nq2; P[4] = P[3] + nq3;
    const int Q = P[4];

    // ---- pass 2: write own row's entries into the flat list ----
    {
        const int fbase = 4 * P[warp];
        if (!fb) {
            int pos = 0;
            #pragma unroll
            for (int c = 0; c < 7; ++c) {
                const int l = c * 32 + lane;
                const bool act = (l < LL) && ((bal[c] >> lane) & 1u);
                const int p = pos + __popc(bal[c] & ((1u << lane) - 1u));
                if (act) s_flat[fbase + p] = (short)(warp * LL + l);
                pos += __popc(bal[c]);
            }
        } else {
            for (int l = lane; l < LL; l += 32)
                s_flat[fbase + l] = (short)(warp * LL + l);
        }
        __syncwarp();
        const int pad = 4 * ((cnt + 3) >> 2) - cnt;
        if (lane < pad) s_flat[fbase + cnt + lane] = s_flat[fbase];
    }
    __syncthreads();

    // ---- balanced quad range for this warp ----
    const int g0 = (Q * warp) >> 2;
    const int g1 = (Q * (warp + 1)) >> 2;

    const float* ikB = ik + (size_t)b0 * LL * DD;
    const float* ivB = iv + (size_t)b0 * LL * DD;
    const unsigned pipe_base =
        (unsigned)__cvta_generic_to_shared(&s_pipe[warp][0][0]);

    // ---- prologue: fill ring via flat list (no row math) ----
    #pragma unroll
    for (int s = 0; s < STAGES; ++s) {
        const int gq = g0 + s;
        if (gq < g1) {
            const int iAB = s_flat[4 * gq + hsel];
            const int iCD = s_flat[4 * gq + 2 + hsel];
            const float* pA = ikB + (size_t)iAB * DD + hl * 4;
            const float* pC = ikB + (size_t)iCD * DD + hl * 4;
            const float* vA = ivB + (size_t)iAB * DD + hl * 4;
            const float* vC = ivB + (size_t)iCD * DD + hl * 4;
            unsigned d = pipe_base + s * 2048 + lane * 16;
            asm volatile(
                "cp.async.cg.shared.global [%0], [%1], 16;\n"
                "cp.async.cg.shared.global [%2], [%3], 16;\n"
                "cp.async.cg.shared.global [%4], [%5], 16;\n"
                "cp.async.cg.shared.global [%6], [%7], 16;\n"
                :: "r"(d), "l"(pA), "r"(d + 512), "l"(pC),
                   "r"(d + 1024), "l"(vA), "r"(d + 1536), "l"(vC) : "memory");
        }
        asm volatile("cp.async.commit_group;" ::: "memory");
    }

    // ---- stream: <=4 row-homogeneous sub-segments, row math hoisted ----
    int slot = 0;
    #pragma unroll
    for (int r = 0; r < WPB; ++r) {
        const int segs = (g0 > P[r])     ? g0 : P[r];
        const int sege = (g1 < P[r + 1]) ? g1 : P[r + 1];
        if (segs >= sege) continue;

        const float4 q0 = ((const float4*)s_q[r])[gl];
        const float4 q1 = ((const float4*)s_q[r])[8 + gl];
        const int nact_r = s_cnt[r];
        const int Pr0    = P[r];

        float sum = 0.f;
        float4 acc0 = make_float4(0.f, 0.f, 0.f, 0.f);
        float4 acc1 = make_float4(0.f, 0.f, 0.f, 0.f);

        for (int t = segs; t < sege; ++t) {
            asm volatile("cp.async.wait_group %0;" :: "n"(STAGES - 1) : "memory");

            const float4* stg = (const float4*)&s_pipe[warp][slot][0];
            const float4 a0 = stg[g * 16 + gl];
            const float4 a1 = stg[g * 16 + 8 + gl];
            const float4 v0 = stg[64 + g * 16 + gl];
            const float4 v1 = stg[64 + g * 16 + 8 + gl];

            const int gp = t + STAGES;
            if (gp < g1) {
                const int iAB = s_flat[4 * gp + hsel];
                const int iCD = s_flat[4 * gp + 2 + hsel];
                const float* pA = ikB + (size_t)iAB * DD + hl * 4;
                const float* pC = ikB + (size_t)iCD * DD + hl * 4;
                const float* vA = ivB + (size_t)iAB * DD + hl * 4;
                const float* vC = ivB + (size_t)iCD * DD + hl * 4;
                unsigned d = pipe_base + slot * 2048 + lane * 16;
                asm volatile(
                    "cp.async.cg.shared.global [%0], [%1], 16;\n"
                    "cp.async.cg.shared.global [%2], [%3], 16;\n"
                    "cp.async.cg.shared.global [%4], [%5], 16;\n"
                    "cp.async.cg.shared.global [%6], [%7], 16;\n"
                    :: "r"(d), "l"(pA), "r"(d + 512), "l"(pC),
                       "r"(d + 1024), "l"(vA), "r"(d + 1536), "l"(vC) : "memory");
            }
            asm volatile("cp.async.commit_group;" ::: "memory");

            // 8-dim partial dot, 3-step butterfly within 8-lane group
            float s = a0.x * q0.x + a0.y * q0.y + a0.z * q0.z + a0.w * q0.w
                    + a1.x * q1.x + a1.y * q1.y + a1.z * q1.z + a1.w * q1.w;
            s += __shfl_xor_sync(0xffffffffu, s, 4);
            s += __shfl_xor_sync(0xffffffffu, s, 2);
            s += __shfl_xor_sync(0xffffffffu, s, 1);

            // fixed-max-0 softmax; padded items get weight 0
            const float w = (4 * (t - Pr0) + g < nact_r) ? __expf(s) : 0.f;
            sum += w;
            acc0.x += w * v0.x; acc0.y += w * v0.y;
            acc0.z += w * v0.z; acc0.w += w * v0.w;
            acc1.x += w * v1.x; acc1.y += w * v1.y;
            acc1.z += w * v1.z; acc1.w += w * v1.w;

            slot = (slot == STAGES - 1) ? 0 : slot + 1;
        }

        // ---- flush this row's partial (once per sub-segment) ----
        #pragma unroll
        for (int o = 8; o <= 16; o <<= 1) {
            sum    += __shfl_xor_sync(0xffffffffu, sum,    o);
            acc0.x += __shfl_xor_sync(0xffffffffu, acc0.x, o);
            acc0.y += __shfl_xor_sync(0xffffffffu, acc0.y, o);
            acc0.z += __shfl_xor_sync(0xffffffffu, acc0.z, o);
            acc0.w += __shfl_xor_sync(0xffffffffu, acc0.w, o);
            acc1.x += __shfl_xor_sync(0xffffffffu, acc1.x, o);
            acc1.y += __shfl_xor_sync(0xffffffffu, acc1.y, o);
            acc1.z += __shfl_xor_sync(0xffffffffu, acc1.z, o);
            acc1.w += __shfl_xor_sync(0xffffffffu, acc1.w, o);
        }
        if (lane < 8) {
            ((float4*)s_part[r][warp])[lane]     = acc0;
            ((float4*)s_part[r][warp])[8 + lane] = acc1;
        }
        if (lane == 0) s_sumw[r][warp] = sum;
    }

    __syncthreads();

    // ---- epilogue: warp w owns output row b0+w ----
    {
        const float tot = s_sumw[warp][0] + s_sumw[warp][1]
                        + s_sumw[warp][2] + s_sumw[warp][3];
        const float invs = 1.f / tot;
        float vx = 0.f, vy = 0.f;
        #pragma unroll
        for (int ws = 0; ws < WPB; ++ws) {
            vx += s_part[warp][ws][2 * lane];
            vy += s_part[warp][ws][2 * lane + 1];
        }
        __syncwarp();
        ((float2*)s_q[warp])[lane] = make_float2(vx * invs, vy * invs);
        __syncwarp();

        float ox = 0.f, oy = 0.f;
        #pragma unroll 8
        for (int j = 0; j < DD; ++j) {
            const float vv = s_q[warp][j];                             // LDS bcast
            const float2 w2 = ((const float2*)(g_WvT + j * DD))[lane]; // coalesced
            ox += vv * w2.x;
            oy += vv * w2.y;
        }
        ((float2*)(out + (size_t)b * DD))[lane] = make_float2(ox, oy);
    }
}

extern "C" void kernel_launch(void* const* d_in, const int* in_sizes, int n_in,
                              void* d_out, int out_size) {
    const float* target_key  = (const float*)d_in[0];
    const float* item_keys   = (const float*)d_in[1];
    const float* item_values = (const float*)d_in[2];
    const int*   mask        = (const int*)  d_in[3];
    const float* W_target    = (const float*)d_in[4];
    const float* W_item      = (const float*)d_in[5];
    const float* W_value     = (const float*)d_in[6];
    float* out = (float*)d_out;

    precompute_kernel<<<DD, DD>>>(W_target, W_item, W_value);
    target_attn_kernel<<<NBLK, 128>>>(target_key, item_keys, item_values,
                                      mask, out);
}

// round 17
// speedup vs baseline: 1.0338x; 1.0195x over previous
#include <cuda_runtime.h>

#define BB 4096
#define LL 200
#define DD 64
#define STAGES 3    // ring of 2KB stages (4 items each)
#define WPB 4       // warps (= rows) per block
#define NBLK (BB / WPB)

__global__ __launch_bounds__(128, 7) void target_attn_kernel(
    const float* __restrict__ tk,    // [B, D]
    const float* __restrict__ ik,    // [B, L, D]
    const float* __restrict__ iv,    // [B, L, D]
    const int*   __restrict__ mask,  // [B, L]
    const float* __restrict__ Wt,    // [D, D] W_target
    const float* __restrict__ Wi,    // [D, D] W_item
    const float* __restrict__ Wv,    // [D, D] W_value
    float* __restrict__ out)         // [B, D]
{
    const int warp = threadIdx.x >> 5;
    const int lane = threadIdx.x & 31;
    const int hl   = lane & 15;      // lane within half-warp (copy addressing)
    const int hsel = lane >> 4;      // 0: items A/C, 1: items B/D
    const int g8   = lane >> 3;      // 8-lane group id 0..3
    const int gl   = lane & 7;       // lane within group
    const int b    = blockIdx.x * WPB + warp;   // one row per warp

    // per-warp ring: stage = [ikA ikB | ikC ikD | ivA ivB | ivC ivD] = 2KB
    __shared__ __align__(16) float s_pipe[WPB][STAGES][512];
    __shared__ __align__(16) float s_q[WPB][DD];
    __shared__ __align__(16) float s_u[WPB][DD];
    __shared__ short s_idx[WPB][LL + 8];

    // ---- per-warp ballot compaction of active indices ----
    const int* mrow = mask + b * LL;
    int base = 0;
    #pragma unroll
    for (int c = 0; c < 7; ++c) {
        const int l = c * 32 + lane;
        const bool act = (l < LL) && (mrow[l] != 0);
        const unsigned bal = __ballot_sync(0xffffffffu, act);
        const int pos = base + __popc(bal & ((1u << lane) - 1u));
        if (act) s_idx[warp][pos] = (short)l;
        base += __popc(bal);
    }
    if (base == 0) {
        // all-masked fallback: softmax(s-1e8)=softmax(s) -> all items active
        #pragma unroll
        for (int c = 0; c < 7; ++c) {
            const int l = c * 32 + lane;
            if (l < LL) s_idx[warp][l] = (short)l;
        }
        base = LL;
    }
    __syncwarp();
    if (lane < 3) s_idx[warp][base + lane] = s_idx[warp][0];  // quad padding
    __syncwarp();
    const int n_act = base;
    const int nquad = (n_act + 3) >> 2;     // iterations (4 items each)

    // ---- load tk into s_q[warp] (needed by butterfly-u below) ----
    {
        float2 t2 = ((const float2*)(tk + (size_t)b * DD))[lane];
        ((float2*)s_q[warp])[lane] = t2;
    }
    __syncwarp();

    // ---- prologue: start cp.async ring (overlaps projection math below) ----
    const float* ikg = ik + (size_t)b * LL * DD;
    const float* ivg = iv + (size_t)b * LL * DD;
    const unsigned pipe_base =
        (unsigned)__cvta_generic_to_shared(&s_pipe[warp][0][0]);

    #pragma unroll
    for (int s = 0; s < STAGES; ++s) {
        if (s < nquad) {
            const int iAB = s_idx[warp][4 * s + hsel];
            const int iCD = s_idx[warp][4 * s + 2 + hsel];
            const float* pA = ikg + (size_t)iAB * DD + hl * 4;
            const float* pC = ikg + (size_t)iCD * DD + hl * 4;
            const float* vA = ivg + (size_t)iAB * DD + hl * 4;
            const float* vC = ivg + (size_t)iCD * DD + hl * 4;
            unsigned d = pipe_base + s * 2048 + lane * 16;
            asm volatile(
                "cp.async.cg.shared.global [%0], [%1], 16;\n"
                "cp.async.cg.shared.global [%2], [%3], 16;\n"
                "cp.async.cg.shared.global [%4], [%5], 16;\n"
                "cp.async.cg.shared.global [%6], [%7], 16;\n"
                :: "r"(d), "l"(pA), "r"(d + 512), "l"(pC),
                   "r"(d + 1024), "l"(vA), "r"(d + 1536), "l"(vC) : "memory");
        }
        asm volatile("cp.async.commit_group;" ::: "memory");
    }

    // ---- u = W_target @ tk via butterfly row-dots (16 iters x 4 groups = 64 rows) ----
    #pragma unroll
    for (int t = 0; t < 16; ++t) {
        const int e = t * 4 + g8;          // row of W_target this group dots
        const float4* wr = (const float4*)(Wt + e * DD);
        const float4 w0 = wr[gl * 2];
        const float4 w1 = wr[gl * 2 + 1];
        const float4 t0 = ((const float4*)s_q[warp])[gl * 2];
        const float4 t1 = ((const float4*)s_q[warp])[gl * 2 + 1];
        float p = w0.x * t0.x + w0.y * t0.y + w0.z * t0.z + w0.w * t0.w
                + w1.x * t1.x + w1.y * t1.y + w1.z * t1.z + w1.w * t1.w;
        p += __shfl_xor_sync(0xffffffffu, p, 4);
        p += __shfl_xor_sync(0xffffffffu, p, 2);
        p += __shfl_xor_sync(0xffffffffu, p, 1);
        if (gl == 0) s_u[warp][e] = p;
    }
    __syncwarp();

    // ---- qk = (W_item^T @ u) * (1/sqrt(D)); naturally coalesced ----
    {
        float qx = 0.f, qy = 0.f;
        #pragma unroll 8
        for (int j = 0; j < DD; ++j) {
            const float uj = s_u[warp][j];                          // LDS bcast
            const float2 w2 = ((const float2*)(Wi + j * DD))[lane]; // coalesced
            qx += uj * w2.x;
            qy += uj * w2.y;
        }
        __syncwarp();
        ((float2*)s_q[warp])[lane] = make_float2(qx * 0.125f, qy * 0.125f);
    }
    __syncwarp();
    // lane's q chunks: dims [4*gl,4*gl+4) and [32+4*gl,36+4*gl)
    const float4 q0 = ((const float4*)s_q[warp])[gl];
    const float4 q1 = ((const float4*)s_q[warp])[8 + gl];

    // ---- streaming loop: 4 items per iteration ----
    float sum = 0.f;
    float4 acc0 = make_float4(0.f, 0.f, 0.f, 0.f);
    float4 acc1 = make_float4(0.f, 0.f, 0.f, 0.f);

    int slot = 0;
    for (int i = 0; i < nquad; ++i) {
        asm volatile("cp.async.wait_group %0;" :: "n"(STAGES - 1) : "memory");

        const float4* stg = (const float4*)&s_pipe[warp][slot][0];
        const float4 a0 = stg[g8 * 16 + gl];           // ik dims [4gl..)
        const float4 a1 = stg[g8 * 16 + 8 + gl];       // ik dims [32+4gl..)
        const float4 v0 = stg[64 + g8 * 16 + gl];      // iv
        const float4 v1 = stg[64 + g8 * 16 + 8 + gl];

        const int pf = i + STAGES;
        if (pf < nquad) {
            const int iAB = s_idx[warp][4 * pf + hsel];
            const int iCD = s_idx[warp][4 * pf + 2 + hsel];
            const float* pA = ikg + (size_t)iAB * DD + hl * 4;
            const float* pC = ikg + (size_t)iCD * DD + hl * 4;
            const float* vA = ivg + (size_t)iAB * DD + hl * 4;
            const float* vC = ivg + (size_t)iCD * DD + hl * 4;
            unsigned d = pipe_base + slot * 2048 + lane * 16;
            asm volatile(
                "cp.async.cg.shared.global [%0], [%1], 16;\n"
                "cp.async.cg.shared.global [%2], [%3], 16;\n"
                "cp.async.cg.shared.global [%4], [%5], 16;\n"
                "cp.async.cg.shared.global [%6], [%7], 16;\n"
                :: "r"(d), "l"(pA), "r"(d + 512), "l"(pC),
                   "r"(d + 1024), "l"(vA), "r"(d + 1536), "l"(vC) : "memory");
        }
        asm volatile("cp.async.commit_group;" ::: "memory");

        // 8-dim partial dot, 3-step butterfly within 8-lane group
        float s = a0.x * q0.x + a0.y * q0.y + a0.z * q0.z + a0.w * q0.w
                + a1.x * q1.x + a1.y * q1.y + a1.z * q1.z + a1.w * q1.w;
        s += __shfl_xor_sync(0xffffffffu, s, 4);
        s += __shfl_xor_sync(0xffffffffu, s, 2);
        s += __shfl_xor_sync(0xffffffffu, s, 1);

        // fixed-max-0 softmax (scores O(1)); sentinel items get weight 0
        const float w = (4 * i + g8 < n_act) ? __expf(s) : 0.f;
        sum += w;
        acc0.x += w * v0.x; acc0.y += w * v0.y;
        acc0.z += w * v0.z; acc0.w += w * v0.w;
        acc1.x += w * v1.x; acc1.y += w * v1.y;
        acc1.z += w * v1.z; acc1.w += w * v1.w;

        slot = (slot == STAGES - 1) ? 0 : slot + 1;
    }

    // ---- merge the 4 item-groups (dims per lane identical across groups) ----
    #pragma unroll
    for (int o = 8; o <= 16; o <<= 1) {
        sum    += __shfl_xor_sync(0xffffffffu, sum,    o);
        acc0.x += __shfl_xor_sync(0xffffffffu, acc0.x, o);
        acc0.y += __shfl_xor_sync(0xffffffffu, acc0.y, o);
        acc0.z += __shfl_xor_sync(0xffffffffu, acc0.z, o);
        acc0.w += __shfl_xor_sync(0xffffffffu, acc0.w, o);
        acc1.x += __shfl_xor_sync(0xffffffffu, acc1.x, o);
        acc1.y += __shfl_xor_sync(0xffffffffu, acc1.y, o);
        acc1.z += __shfl_xor_sync(0xffffffffu, acc1.z, o);
        acc1.w += __shfl_xor_sync(0xffffffffu, acc1.w, o);
    }
    const float invs = 1.f / sum;

    __syncwarp();
    if (lane < 8) {   // lanes 0..7: gl == lane
        float4 o0 = make_float4(acc0.x * invs, acc0.y * invs,
                                acc0.z * invs, acc0.w * invs);
        float4 o1 = make_float4(acc1.x * invs, acc1.y * invs,
                                acc1.z * invs, acc1.w * invs);
        ((float4*)s_q[warp])[lane]     = o0;   // vbar dims [4l..4l+4)
        ((float4*)s_q[warp])[8 + lane] = o1;   // vbar dims [32+4l..)
    }
    __syncwarp();

    // ---- out = Wv @ vbar via butterfly row-dots (16 iters) + coalesced store ----
    #pragma unroll
    for (int t = 0; t < 16; ++t) {
        const int e = t * 4 + g8;
        const float4* wr = (const float4*)(Wv + e * DD);
        const float4 w0 = wr[gl * 2];
        const float4 w1 = wr[gl * 2 + 1];
        const float4 v0 = ((const float4*)s_q[warp])[gl * 2];
        const float4 v1 = ((const float4*)s_q[warp])[gl * 2 + 1];
        float p = w0.x * v0.x + w0.y * v0.y + w0.z * v0.z + w0.w * v0.w
                + w1.x * v1.x + w1.y * v1.y + w1.z * v1.z + w1.w * v1.w;
        p += __shfl_xor_sync(0xffffffffu, p, 4);
        p += __shfl_xor_sync(0xffffffffu, p, 2);
        p += __shfl_xor_sync(0xffffffffu, p, 1);
        if (gl == 0) s_u[warp][e] = p;
    }
    __syncwarp();
    {
        const float2 o2 = ((const float2*)s_u[warp])[lane];
        ((float2*)(out + (size_t)b * DD))[lane] = o2;
    }
}

extern "C" void kernel_launch(void* const* d_in, const int* in_sizes, int n_in,
                              void* d_out, int out_size) {
    const float* target_key  = (const float*)d_in[0];
    const float* item_keys   = (const float*)d_in[1];
    const float* item_values = (const float*)d_in[2];
    const int*   mask        = (const int*)  d_in[3];
    const float* W_target    = (const float*)d_in[4];
    const float* W_item      = (const float*)d_in[5];
    const float* W_value     = (const float*)d_in[6];
    float* out = (float*)d_out;

    target_attn_kernel<<<NBLK, 128>>>(target_key, item_keys, item_values,
                                      mask, W_target, W_item, W_value, out);
}